// round 15
// baseline (speedup 1.0000x reference)
#include <cuda_runtime.h>
#include <cuda_fp16.h>
#include <math.h>

#define MAX_NODES 50000
#define MAX_RELS  16

// Scratch (device globals; no allocation allowed)
// g_Ph layout: [n][col][basis] halves (128 halves per node; col-major pairs)
__device__ __align__(16) __half g_Ph[MAX_NODES * 128];
__device__ __align__(16) __half g_uh[MAX_NODES * 32];    // [n][col]
__device__ __align__(16) __half g_vh[MAX_NODES * 32];    // [n][col]
__device__ __align__(16) float  g_agg[MAX_NODES * 32];   // curr + scatter
__device__ __align__(16) float  g_t[MAX_RELS * 32];      // attn bias table

__device__ __forceinline__ float tf32r(float x) {
    unsigned r;
    asm("cvt.rna.tf32.f32 %0, %1;" : "=r"(r) : "f"(x));
    return __uint_as_float(r);
}
__device__ __forceinline__ unsigned f2u(float x) { return __float_as_uint(x); }
__device__ __forceinline__ unsigned h2bits(__half2 h) {
    return *reinterpret_cast<unsigned*>(&h);
}

__device__ __forceinline__ void mma_tf32(
    float* d, unsigned a0, unsigned a1, unsigned a2, unsigned a3,
    unsigned b0, unsigned b1) {
    asm("mma.sync.aligned.m16n8k8.row.col.f32.tf32.tf32.f32 "
        "{%0,%1,%2,%3},{%4,%5,%6,%7},{%8,%9},{%0,%1,%2,%3};"
        : "+f"(d[0]), "+f"(d[1]), "+f"(d[2]), "+f"(d[3])
        : "r"(a0), "r"(a1), "r"(a2), "r"(a3), "r"(b0), "r"(b1));
}

// dynamic smem layout (floats):
//   sBfA: 1024 float2 = 2048 floats   [ (kk*4+nt)*32 + lane ]
//   sBfB: 3584 float2 = 7168 floats   [ ((t*4+s)*4+kk)*32 + lane ]
//   sX:   8 warps * 16*68 = 8704 floats
#define BFB_OFF 2048
#define SX_OFF  9216
#define SMEM_FLOATS (9216 + 8704)
#define SMEM_BYTES (SMEM_FLOATS * 4)

// ---------------------------------------------------------------------------
// K1: node stage via tensor cores (mma.m16n8k8.tf32). 16 nodes per warp-task,
// ~2 tasks per warp (grid-stride). Block prologue packs all mma B-operands
// into smem in per-lane fragment order. Block 0 also builds g_t.
// ---------------------------------------------------------------------------
__global__ void __launch_bounds__(256) k_node(
    const float* __restrict__ feat, const float* __restrict__ embed,
    const int* __restrict__ idx, const float* __restrict__ transform,
    const float* __restrict__ weight, const float* __restrict__ A_w,
    const float* __restrict__ selfw, const float* __restrict__ attn_emb,
    const float* __restrict__ A_b, float* __restrict__ out, int n_nodes) {
    extern __shared__ float smem_dyn[];
    float2* sBfA = reinterpret_cast<float2*>(smem_dyn);
    float2* sBfB = reinterpret_cast<float2*>(smem_dyn + BFB_OFF);

    int tid = threadIdx.x;

    // g_t (block 0): t[r][o] = A_b[o] + sum_k attn_emb[r,k] * A_w[64+k, o]
    if (blockIdx.x == 0) {
        int r0 = tid >> 5;
        int o = tid & 31;
#pragma unroll
        for (int rr = 0; rr < 2; rr++) {
            int r = r0 + rr * 8;
            float acc = A_b[o];
#pragma unroll
            for (int k = 0; k < 32; k++)
                acc += attn_emb[r * 32 + k] * A_w[(64 + k) * 32 + o];
            g_t[r * 32 + o] = acc;
        }
    }

    // Phase A B-fragments: transform[64x32]; mma index (kk, nt)
    for (int i = tid; i < 1024; i += 256) {
        int lane = i & 31, nt = (i >> 5) & 3, kk = i >> 7;
        int gid = lane >> 2, t4 = lane & 3;
        int k0 = kk * 8 + t4, o = nt * 8 + gid;
        sBfA[i] = make_float2(tf32r(transform[k0 * 32 + o]),
                              tf32r(transform[(k0 + 4) * 32 + o]));
    }
    // Phase B B-fragments: 7 tables [32x32]; mma index (t, s, kk)
    for (int i = tid; i < 3584; i += 256) {
        int lane = i & 31, kk = (i >> 5) & 3, s = (i >> 7) & 3, t = i >> 9;
        int gid = lane >> 2, t4 = lane & 3;
        int o = s * 8 + gid;
        int k = kk * 8 + t4;
        int r0 = k * 32 + o, r1 = (k + 4) * 32 + o;
        float vx, vy;
        if (t < 4)       { vx = weight[t * 1024 + r0]; vy = weight[t * 1024 + r1]; }
        else if (t == 4) { vx = A_w[r0];               vy = A_w[r1]; }
        else if (t == 5) { vx = A_w[1024 + r0];        vy = A_w[1024 + r1]; }
        else             { vx = selfw[r0];             vy = selfw[r1]; }
        sBfB[i] = make_float2(tf32r(vx), tf32r(vy));
    }
    __syncthreads();

    int lane = tid & 31;
    int w = tid >> 5;
    float* sXw = smem_dyn + SX_OFF + w * 1088;   // [16][68]

    int gid = lane >> 2;    // 0..7
    int tid4 = lane & 3;    // 0..3

    int n_tasks = (n_nodes + 15) >> 4;
    int task_stride = gridDim.x * 8;

    for (int task = blockIdx.x * 8 + w; task < n_tasks; task += task_stride) {
        int n0 = task * 16;

        // ---- stage X = [feat | embed[idx]] as tf32, rows 16 x cols 64 ----
        int iIdx = 0;
        if (lane < 16 && n0 + lane < n_nodes) iIdx = idx[n0 + lane];
#pragma unroll
        for (int it = 0; it < 8; it++) {
            int r = it * 2 + (lane >> 4);   // 0..15
            int f4 = lane & 15;             // col group of 4
            int n = n0 + r;
            int e = __shfl_sync(0xffffffffu, iIdx, r);
            float4 vle = make_float4(0.f, 0.f, 0.f, 0.f);
            if (n < n_nodes) {
                if (f4 < 8)
                    vle = *reinterpret_cast<const float4*>(&feat[(size_t)n * 32 + f4 * 4]);
                else
                    vle = *reinterpret_cast<const float4*>(&embed[(size_t)e * 32 + (f4 - 8) * 4]);
            }
            float4 tv = make_float4(tf32r(vle.x), tf32r(vle.y), tf32r(vle.z), tf32r(vle.w));
            *reinterpret_cast<float4*>(&sXw[r * 68 + f4 * 4]) = tv;
        }
        __syncwarp();

        // ---- Phase A: 8 k-steps x 4 n-tiles ----
        float accA[4][4];
#pragma unroll
        for (int nt = 0; nt < 4; nt++)
#pragma unroll
            for (int i = 0; i < 4; i++) accA[nt][i] = 0.f;

#pragma unroll
        for (int kk = 0; kk < 8; kk++) {
            int kb = kk * 8;
            unsigned a0 = f2u(sXw[gid * 68 + kb + tid4]);
            unsigned a1 = f2u(sXw[(gid + 8) * 68 + kb + tid4]);
            unsigned a2 = f2u(sXw[gid * 68 + kb + tid4 + 4]);
            unsigned a3 = f2u(sXw[(gid + 8) * 68 + kb + tid4 + 4]);
#pragma unroll
            for (int nt = 0; nt < 4; nt++) {
                float2 b = sBfA[(kk * 4 + nt) * 32 + lane];
                mma_tf32(accA[nt], a0, a1, a2, a3, f2u(b.x), f2u(b.y));
            }
        }
        __syncwarp();   // all reads of sXw done before overwrite

        int n_a = n0 + gid;
        int n_b = n0 + gid + 8;
        // store out[:,0,:] (fp32) and stage fea (tf32) back into sXw
#pragma unroll
        for (int nt = 0; nt < 4; nt++) {
            int c = nt * 8 + 2 * tid4;
            if (n_a < n_nodes)
                *reinterpret_cast<float2*>(&out[(size_t)n_a * 64 + c]) =
                    make_float2(accA[nt][0], accA[nt][1]);
            if (n_b < n_nodes)
                *reinterpret_cast<float2*>(&out[(size_t)n_b * 64 + c]) =
                    make_float2(accA[nt][2], accA[nt][3]);
            *reinterpret_cast<float2*>(&sXw[gid * 68 + c]) =
                make_float2(tf32r(accA[nt][0]), tf32r(accA[nt][1]));
            *reinterpret_cast<float2*>(&sXw[(gid + 8) * 68 + c]) =
                make_float2(tf32r(accA[nt][2]), tf32r(accA[nt][3]));
        }
        __syncwarp();

        // ---- Phase B: A-frags for fea [16x32], 4 k-steps ----
        unsigned af[4][4];
#pragma unroll
        for (int kk = 0; kk < 4; kk++) {
            int kb = kk * 8;
            af[kk][0] = f2u(sXw[gid * 68 + kb + tid4]);
            af[kk][1] = f2u(sXw[(gid + 8) * 68 + kb + tid4]);
            af[kk][2] = f2u(sXw[gid * 68 + kb + tid4 + 4]);
            af[kk][3] = f2u(sXw[(gid + 8) * 68 + kb + tid4 + 4]);
        }

        // P bases (t=0..3), s-outer so per-col basis quads pack into uint4
#pragma unroll
        for (int s = 0; s < 4; s++) {
            float pa0[4], pa1[4], pb0[4], pb1[4];
#pragma unroll
            for (int t = 0; t < 4; t++) {
                float d[4] = {0.f, 0.f, 0.f, 0.f};
#pragma unroll
                for (int kk = 0; kk < 4; kk++) {
                    float2 b = sBfB[((t * 4 + s) * 4 + kk) * 32 + lane];
                    mma_tf32(d, af[kk][0], af[kk][1], af[kk][2], af[kk][3],
                             f2u(b.x), f2u(b.y));
                }
                pa0[t] = d[0]; pa1[t] = d[1]; pb0[t] = d[2]; pb1[t] = d[3];
            }
            int c = s * 8 + 2 * tid4;   // even col
            if (n_a < n_nodes) {
                uint4 pk;
                pk.x = h2bits(__floats2half2_rn(pa0[0], pa0[1]));
                pk.y = h2bits(__floats2half2_rn(pa0[2], pa0[3]));
                pk.z = h2bits(__floats2half2_rn(pa1[0], pa1[1]));
                pk.w = h2bits(__floats2half2_rn(pa1[2], pa1[3]));
                *reinterpret_cast<uint4*>(&g_Ph[(size_t)n_a * 128 + c * 4]) = pk;
            }
            if (n_b < n_nodes) {
                uint4 pk;
                pk.x = h2bits(__floats2half2_rn(pb0[0], pb0[1]));
                pk.y = h2bits(__floats2half2_rn(pb0[2], pb0[3]));
                pk.z = h2bits(__floats2half2_rn(pb1[0], pb1[1]));
                pk.w = h2bits(__floats2half2_rn(pb1[2], pb1[3]));
                *reinterpret_cast<uint4*>(&g_Ph[(size_t)n_b * 128 + c * 4]) = pk;
            }
        }

        // u, v, selfloop (t=4..6)
#pragma unroll
        for (int t = 4; t < 7; t++) {
#pragma unroll
            for (int s = 0; s < 4; s++) {
                float d[4] = {0.f, 0.f, 0.f, 0.f};
#pragma unroll
                for (int kk = 0; kk < 4; kk++) {
                    float2 b = sBfB[((t * 4 + s) * 4 + kk) * 32 + lane];
                    mma_tf32(d, af[kk][0], af[kk][1], af[kk][2], af[kk][3],
                             f2u(b.x), f2u(b.y));
                }
                int col = s * 8 + 2 * tid4;
                if (t == 4) {
                    if (n_a < n_nodes)
                        *reinterpret_cast<__half2*>(&g_uh[(size_t)n_a * 32 + col]) =
                            __floats2half2_rn(d[0], d[1]);
                    if (n_b < n_nodes)
                        *reinterpret_cast<__half2*>(&g_uh[(size_t)n_b * 32 + col]) =
                            __floats2half2_rn(d[2], d[3]);
                } else if (t == 5) {
                    if (n_a < n_nodes)
                        *reinterpret_cast<__half2*>(&g_vh[(size_t)n_a * 32 + col]) =
                            __floats2half2_rn(d[0], d[1]);
                    if (n_b < n_nodes)
                        *reinterpret_cast<__half2*>(&g_vh[(size_t)n_b * 32 + col]) =
                            __floats2half2_rn(d[2], d[3]);
                } else {
                    if (n_a < n_nodes)
                        *reinterpret_cast<float2*>(&g_agg[(size_t)n_a * 32 + col]) =
                            make_float2(d[0], d[1]);
                    if (n_b < n_nodes)
                        *reinterpret_cast<float2*>(&g_agg[(size_t)n_b * 32 + col]) =
                            make_float2(d[2], d[3]);
                }
            }
        }
        __syncwarp();   // sXw reuse across grid-stride iterations
    }
}

// ---------------------------------------------------------------------------
// K2: edge stage. 16 edges per warp (4 quads, all gathers issued up-front);
// 8 lanes per edge; each lane covers 4 output columns.
// g_Ph layout: [n][col][basis] -> per lane 2x LDG.128.
// ---------------------------------------------------------------------------
__global__ void __launch_bounds__(256) k_edge(
    const int* __restrict__ esrc, const int* __restrict__ edst,
    const int* __restrict__ etype, const float* __restrict__ w_comp,
    const float* __restrict__ B_w, const float* __restrict__ B_b, int n_edges) {
    __shared__ __align__(16) float4 s_wc[MAX_RELS];
    __shared__ __align__(16) float4 s_t4[MAX_RELS * 8];
    __shared__ __align__(16) float4 s_bw4[8];
    __shared__ float s_bb;

    int tid = threadIdx.x;
    if (tid < MAX_RELS)
        s_wc[tid] = reinterpret_cast<const float4*>(w_comp)[tid];
    if (tid < MAX_RELS * 8)
        s_t4[tid] = reinterpret_cast<const float4*>(g_t)[tid];
    if (tid < 8)
        s_bw4[tid] = reinterpret_cast<const float4*>(B_w)[tid];
    if (tid == 0) s_bb = B_b[0];
    __syncthreads();

    int warp = (blockIdx.x * blockDim.x + tid) >> 5;
    int lane = tid & 31;
    int sub = lane >> 3;
    int g = lane & 7;
    float4 bw = s_bw4[g];

    int src[4], dst[4], ty[4];
    bool ok[4];
#pragma unroll
    for (int q = 0; q < 4; q++) {
        int e = warp * 16 + q * 4 + sub;
        ok[q] = (e < n_edges);
        int ee = ok[q] ? e : 0;
        src[q] = esrc[ee];
        dst[q] = edst[ee];
        ty[q] = etype[ee];
    }
    if (!ok[0]) return;

    // all gathers issued before any consumption (deep MLP)
    uint4 r0[4], r1[4];
    uint2 uu[4], vv[4];
#pragma unroll
    for (int q = 0; q < 4; q++) {
        const uint4* Pp =
            reinterpret_cast<const uint4*>(g_Ph + (size_t)src[q] * 128 + 16 * g);
        r0[q] = Pp[0];
        r1[q] = Pp[1];
        uu[q] = *reinterpret_cast<const uint2*>(g_uh + (size_t)src[q] * 32 + g * 4);
        vv[q] = *reinterpret_cast<const uint2*>(g_vh + (size_t)dst[q] * 32 + g * 4);
    }

#pragma unroll
    for (int q = 0; q < 4; q++) {
        if (!ok[q]) break;
        float4 cc = s_wc[ty[q]];
        float4 t4 = s_t4[ty[q] * 8 + g];

        // cols 4g..4g+3; per col the 4 basis values are contiguous halves
        float2 c0a = __half22float2(*reinterpret_cast<__half2*>(&r0[q].x));
        float2 c0b = __half22float2(*reinterpret_cast<__half2*>(&r0[q].y));
        float2 c1a = __half22float2(*reinterpret_cast<__half2*>(&r0[q].z));
        float2 c1b = __half22float2(*reinterpret_cast<__half2*>(&r0[q].w));
        float2 c2a = __half22float2(*reinterpret_cast<__half2*>(&r1[q].x));
        float2 c2b = __half22float2(*reinterpret_cast<__half2*>(&r1[q].y));
        float2 c3a = __half22float2(*reinterpret_cast<__half2*>(&r1[q].z));
        float2 c3b = __half22float2(*reinterpret_cast<__half2*>(&r1[q].w));

        float4 msg;
        msg.x = c0a.x * cc.x + c0a.y * cc.y + c0b.x * cc.z + c0b.y * cc.w;
        msg.y = c1a.x * cc.x + c1a.y * cc.y + c1b.x * cc.z + c1b.y * cc.w;
        msg.z = c2a.x * cc.x + c2a.y * cc.y + c2b.x * cc.z + c2b.y * cc.w;
        msg.w = c3a.x * cc.x + c3a.y * cc.y + c3b.x * cc.z + c3b.y * cc.w;

        float2 u0 = __half22float2(*reinterpret_cast<__half2*>(&uu[q].x));
        float2 u1 = __half22float2(*reinterpret_cast<__half2*>(&uu[q].y));
        float2 v0 = __half22float2(*reinterpret_cast<__half2*>(&vv[q].x));
        float2 v1 = __half22float2(*reinterpret_cast<__half2*>(&vv[q].y));

        float zx = fmaxf(u0.x + v0.x + t4.x, 0.f);
        float zy = fmaxf(u0.y + v0.y + t4.y, 0.f);
        float zz = fmaxf(u1.x + v1.x + t4.z, 0.f);
        float zw = fmaxf(u1.y + v1.y + t4.w, 0.f);

        float s = zx * bw.x + zy * bw.y + zz * bw.z + zw * bw.w;
        s += __shfl_xor_sync(0xffffffffu, s, 4);
        s += __shfl_xor_sync(0xffffffffu, s, 2);
        s += __shfl_xor_sync(0xffffffffu, s, 1);
        float a = 1.f / (1.f + __expf(-(s + s_bb)));

        float4 r = make_float4(a * msg.x, a * msg.y, a * msg.z, a * msg.w);
        atomicAdd(reinterpret_cast<float4*>(g_agg) + (size_t)dst[q] * 8 + g, r);
    }
}

// ---------------------------------------------------------------------------
// K3: h = relu(agg) -> out[:,1,:]  (float4 vectorized)
// ---------------------------------------------------------------------------
__global__ void k_final(float* __restrict__ out, int n4) {
    int i = blockIdx.x * blockDim.x + threadIdx.x;
    if (i >= n4) return;
    int n = i >> 3;
    int q = i & 7;
    float4 v = reinterpret_cast<const float4*>(g_agg)[i];
    float4 r = make_float4(fmaxf(v.x, 0.f), fmaxf(v.y, 0.f),
                           fmaxf(v.z, 0.f), fmaxf(v.w, 0.f));
    reinterpret_cast<float4*>(out)[(size_t)n * 16 + 8 + q] = r;
}

extern "C" void kernel_launch(void* const* d_in, const int* in_sizes, int n_in,
                              void* d_out, int out_size) {
    const float* feat      = (const float*)d_in[0];
    const float* embed     = (const float*)d_in[1];
    const float* transform = (const float*)d_in[2];
    const float* weight    = (const float*)d_in[3];
    const float* w_comp    = (const float*)d_in[4];
    const float* selfw     = (const float*)d_in[5];
    const float* A_w       = (const float*)d_in[6];
    const float* A_b       = (const float*)d_in[7];
    const float* B_w       = (const float*)d_in[8];
    const float* B_b       = (const float*)d_in[9];
    const float* attn_emb  = (const float*)d_in[10];
    const int*   idx       = (const int*)d_in[11];
    const int*   esrc      = (const int*)d_in[12];
    const int*   edst      = (const int*)d_in[13];
    const int*   ety       = (const int*)d_in[14];
    float* out = (float*)d_out;

    int n_nodes = in_sizes[0] / 32;
    int n_edges = in_sizes[12];

    cudaFuncSetAttribute(k_node, cudaFuncAttributeMaxDynamicSharedMemorySize,
                         SMEM_BYTES);

    int n_tasks = (n_nodes + 15) / 16;          // 3125
    int blocks1 = (n_tasks + 15) / 16;          // ~2 tasks/warp
    k_node<<<blocks1, 256, SMEM_BYTES>>>(feat, embed, idx, transform, weight,
                                         A_w, selfw, attn_emb, A_b, out,
                                         n_nodes);

    int blocks2 = (n_edges + 127) / 128;        // 8 warps/block, 16 edges/warp
    k_edge<<<blocks2, 256>>>(esrc, edst, ety, w_comp, B_w, B_b, n_edges);

    int n4 = n_nodes * 8;
    int blocks3 = (n4 + 255) / 256;
    k_final<<<blocks3, 256>>>(out, n4);
}

// round 16
// speedup vs baseline: 1.0967x; 1.0967x over previous
#include <cuda_runtime.h>
#include <cuda_fp16.h>
#include <math.h>

#define MAX_NODES 50000
#define MAX_RELS  16

// Scratch (device globals; no allocation allowed)
// g_Ph layout: [n][col][basis] halves (128 halves per node)
__device__ __align__(16) __half g_Ph[MAX_NODES * 128];
__device__ __align__(16) __half g_uh[MAX_NODES * 32];    // [n][col]
__device__ __align__(16) __half g_vh[MAX_NODES * 32];    // [n][col]
__device__ __align__(16) float  g_agg[MAX_NODES * 32];   // curr + scatter
__device__ __align__(16) float  g_t[MAX_RELS * 32];      // attn bias table

__device__ __forceinline__ float tf32r(float x) {
    unsigned r;
    asm("cvt.rna.tf32.f32 %0, %1;" : "=r"(r) : "f"(x));
    return __uint_as_float(r);
}
__device__ __forceinline__ unsigned f2u(float x) { return __float_as_uint(x); }
__device__ __forceinline__ unsigned h2bits(__half2 h) {
    return *reinterpret_cast<unsigned*>(&h);
}

__device__ __forceinline__ void mma_tf32(
    float* d, unsigned a0, unsigned a1, unsigned a2, unsigned a3,
    unsigned b0, unsigned b1) {
    asm("mma.sync.aligned.m16n8k8.row.col.f32.tf32.tf32.f32 "
        "{%0,%1,%2,%3},{%4,%5,%6,%7},{%8,%9},{%0,%1,%2,%3};"
        : "+f"(d[0]), "+f"(d[1]), "+f"(d[2]), "+f"(d[3])
        : "r"(a0), "r"(a1), "r"(a2), "r"(a3), "r"(b0), "r"(b1));
}

// dynamic smem layout (floats):
//   sBfA: 1024 float2 = 2048 floats   [ (kk*4+nt)*32 + lane ]
//   sBfB: 3584 float2 = 7168 floats   [ ((t*4+s)*4+kk)*32 + lane ]
//   sX:   8 warps * 16*68 = 8704 floats
#define BFB_OFF 2048
#define SX_OFF  9216
#define SMEM_FLOATS (9216 + 8704)
#define SMEM_BYTES (SMEM_FLOATS * 4)

// ---------------------------------------------------------------------------
// K1: node stage via tensor cores (mma.m16n8k8.tf32). 16 nodes per warp,
// one task per warp (grid 391 — ~2.6 blocks/SM, single balanced wave).
// Block prologue packs all mma B-operands into smem in per-lane fragment
// order. Block 0 also builds g_t.
// ---------------------------------------------------------------------------
__global__ void __launch_bounds__(256) k_node(
    const float* __restrict__ feat, const float* __restrict__ embed,
    const int* __restrict__ idx, const float* __restrict__ transform,
    const float* __restrict__ weight, const float* __restrict__ A_w,
    const float* __restrict__ selfw, const float* __restrict__ attn_emb,
    const float* __restrict__ A_b, float* __restrict__ out, int n_nodes) {
    extern __shared__ float smem_dyn[];
    float2* sBfA = reinterpret_cast<float2*>(smem_dyn);
    float2* sBfB = reinterpret_cast<float2*>(smem_dyn + BFB_OFF);

    int tid = threadIdx.x;

    // g_t (block 0): t[r][o] = A_b[o] + sum_k attn_emb[r,k] * A_w[64+k, o]
    if (blockIdx.x == 0) {
        int r0 = tid >> 5;
        int o = tid & 31;
#pragma unroll
        for (int rr = 0; rr < 2; rr++) {
            int r = r0 + rr * 8;
            float acc = A_b[o];
#pragma unroll
            for (int k = 0; k < 32; k++)
                acc += attn_emb[r * 32 + k] * A_w[(64 + k) * 32 + o];
            g_t[r * 32 + o] = acc;
        }
    }

    // Phase A B-fragments: transform[64x32]; mma index (kk, nt)
    for (int i = tid; i < 1024; i += 256) {
        int lane = i & 31, nt = (i >> 5) & 3, kk = i >> 7;
        int gid = lane >> 2, t4 = lane & 3;
        int k0 = kk * 8 + t4, o = nt * 8 + gid;
        sBfA[i] = make_float2(tf32r(transform[k0 * 32 + o]),
                              tf32r(transform[(k0 + 4) * 32 + o]));
    }
    // Phase B B-fragments: 7 tables [32x32]; mma index (t, s, kk)
    for (int i = tid; i < 3584; i += 256) {
        int lane = i & 31, kk = (i >> 5) & 3, s = (i >> 7) & 3, t = i >> 9;
        int gid = lane >> 2, t4 = lane & 3;
        int o = s * 8 + gid;
        int k = kk * 8 + t4;
        int r0 = k * 32 + o, r1 = (k + 4) * 32 + o;
        float vx, vy;
        if (t < 4)       { vx = weight[t * 1024 + r0]; vy = weight[t * 1024 + r1]; }
        else if (t == 4) { vx = A_w[r0];               vy = A_w[r1]; }
        else if (t == 5) { vx = A_w[1024 + r0];        vy = A_w[1024 + r1]; }
        else             { vx = selfw[r0];             vy = selfw[r1]; }
        sBfB[i] = make_float2(tf32r(vx), tf32r(vy));
    }
    __syncthreads();

    int lane = tid & 31;
    int w = tid >> 5;
    float* sXw = smem_dyn + SX_OFF + w * 1088;   // [16][68]

    int gid = lane >> 2;    // 0..7
    int tid4 = lane & 3;    // 0..3

    int n_tasks = (n_nodes + 15) >> 4;
    int task = blockIdx.x * 8 + w;
    if (task >= n_tasks) return;
    int n0 = task * 16;

    // ---- stage X = [feat | embed[idx]] as tf32, rows 16 x cols 64 ----
    int iIdx = 0;
    if (lane < 16 && n0 + lane < n_nodes) iIdx = idx[n0 + lane];
#pragma unroll
    for (int it = 0; it < 8; it++) {
        int r = it * 2 + (lane >> 4);   // 0..15
        int f4 = lane & 15;             // col group of 4
        int n = n0 + r;
        int e = __shfl_sync(0xffffffffu, iIdx, r);
        float4 vle = make_float4(0.f, 0.f, 0.f, 0.f);
        if (n < n_nodes) {
            if (f4 < 8)
                vle = *reinterpret_cast<const float4*>(&feat[(size_t)n * 32 + f4 * 4]);
            else
                vle = *reinterpret_cast<const float4*>(&embed[(size_t)e * 32 + (f4 - 8) * 4]);
        }
        float4 tv = make_float4(tf32r(vle.x), tf32r(vle.y), tf32r(vle.z), tf32r(vle.w));
        *reinterpret_cast<float4*>(&sXw[r * 68 + f4 * 4]) = tv;
    }
    __syncwarp();

    // ---- Phase A: 8 k-steps x 4 n-tiles ----
    float accA[4][4];
#pragma unroll
    for (int nt = 0; nt < 4; nt++)
#pragma unroll
        for (int i = 0; i < 4; i++) accA[nt][i] = 0.f;

#pragma unroll
    for (int kk = 0; kk < 8; kk++) {
        int kb = kk * 8;
        unsigned a0 = f2u(sXw[gid * 68 + kb + tid4]);
        unsigned a1 = f2u(sXw[(gid + 8) * 68 + kb + tid4]);
        unsigned a2 = f2u(sXw[gid * 68 + kb + tid4 + 4]);
        unsigned a3 = f2u(sXw[(gid + 8) * 68 + kb + tid4 + 4]);
#pragma unroll
        for (int nt = 0; nt < 4; nt++) {
            float2 b = sBfA[(kk * 4 + nt) * 32 + lane];
            mma_tf32(accA[nt], a0, a1, a2, a3, f2u(b.x), f2u(b.y));
        }
    }
    __syncwarp();   // all reads of sXw done before overwrite

    int n_a = n0 + gid;
    int n_b = n0 + gid + 8;
    // store out[:,0,:] (fp32) and stage fea (tf32) back into sXw
#pragma unroll
    for (int nt = 0; nt < 4; nt++) {
        int c = nt * 8 + 2 * tid4;
        if (n_a < n_nodes)
            *reinterpret_cast<float2*>(&out[(size_t)n_a * 64 + c]) =
                make_float2(accA[nt][0], accA[nt][1]);
        if (n_b < n_nodes)
            *reinterpret_cast<float2*>(&out[(size_t)n_b * 64 + c]) =
                make_float2(accA[nt][2], accA[nt][3]);
        *reinterpret_cast<float2*>(&sXw[gid * 68 + c]) =
            make_float2(tf32r(accA[nt][0]), tf32r(accA[nt][1]));
        *reinterpret_cast<float2*>(&sXw[(gid + 8) * 68 + c]) =
            make_float2(tf32r(accA[nt][2]), tf32r(accA[nt][3]));
    }
    __syncwarp();

    // ---- Phase B: A-frags for fea [16x32], 4 k-steps ----
    unsigned af[4][4];
#pragma unroll
    for (int kk = 0; kk < 4; kk++) {
        int kb = kk * 8;
        af[kk][0] = f2u(sXw[gid * 68 + kb + tid4]);
        af[kk][1] = f2u(sXw[(gid + 8) * 68 + kb + tid4]);
        af[kk][2] = f2u(sXw[gid * 68 + kb + tid4 + 4]);
        af[kk][3] = f2u(sXw[(gid + 8) * 68 + kb + tid4 + 4]);
    }

    // P bases (t=0..3), s-outer so per-col basis quads pack into uint4
#pragma unroll
    for (int s = 0; s < 4; s++) {
        float pa0[4], pa1[4], pb0[4], pb1[4];
#pragma unroll
        for (int t = 0; t < 4; t++) {
            float d[4] = {0.f, 0.f, 0.f, 0.f};
#pragma unroll
            for (int kk = 0; kk < 4; kk++) {
                float2 b = sBfB[((t * 4 + s) * 4 + kk) * 32 + lane];
                mma_tf32(d, af[kk][0], af[kk][1], af[kk][2], af[kk][3],
                         f2u(b.x), f2u(b.y));
            }
            pa0[t] = d[0]; pa1[t] = d[1]; pb0[t] = d[2]; pb1[t] = d[3];
        }
        int c = s * 8 + 2 * tid4;   // even col
        if (n_a < n_nodes) {
            uint4 pk;
            pk.x = h2bits(__floats2half2_rn(pa0[0], pa0[1]));
            pk.y = h2bits(__floats2half2_rn(pa0[2], pa0[3]));
            pk.z = h2bits(__floats2half2_rn(pa1[0], pa1[1]));
            pk.w = h2bits(__floats2half2_rn(pa1[2], pa1[3]));
            *reinterpret_cast<uint4*>(&g_Ph[(size_t)n_a * 128 + c * 4]) = pk;
        }
        if (n_b < n_nodes) {
            uint4 pk;
            pk.x = h2bits(__floats2half2_rn(pb0[0], pb0[1]));
            pk.y = h2bits(__floats2half2_rn(pb0[2], pb0[3]));
            pk.z = h2bits(__floats2half2_rn(pb1[0], pb1[1]));
            pk.w = h2bits(__floats2half2_rn(pb1[2], pb1[3]));
            *reinterpret_cast<uint4*>(&g_Ph[(size_t)n_b * 128 + c * 4]) = pk;
        }
    }

    // u, v, selfloop (t=4..6)
#pragma unroll
    for (int t = 4; t < 7; t++) {
#pragma unroll
        for (int s = 0; s < 4; s++) {
            float d[4] = {0.f, 0.f, 0.f, 0.f};
#pragma unroll
            for (int kk = 0; kk < 4; kk++) {
                float2 b = sBfB[((t * 4 + s) * 4 + kk) * 32 + lane];
                mma_tf32(d, af[kk][0], af[kk][1], af[kk][2], af[kk][3],
                         f2u(b.x), f2u(b.y));
            }
            int col = s * 8 + 2 * tid4;
            if (t == 4) {
                if (n_a < n_nodes)
                    *reinterpret_cast<__half2*>(&g_uh[(size_t)n_a * 32 + col]) =
                        __floats2half2_rn(d[0], d[1]);
                if (n_b < n_nodes)
                    *reinterpret_cast<__half2*>(&g_uh[(size_t)n_b * 32 + col]) =
                        __floats2half2_rn(d[2], d[3]);
            } else if (t == 5) {
                if (n_a < n_nodes)
                    *reinterpret_cast<__half2*>(&g_vh[(size_t)n_a * 32 + col]) =
                        __floats2half2_rn(d[0], d[1]);
                if (n_b < n_nodes)
                    *reinterpret_cast<__half2*>(&g_vh[(size_t)n_b * 32 + col]) =
                        __floats2half2_rn(d[2], d[3]);
            } else {
                if (n_a < n_nodes)
                    *reinterpret_cast<float2*>(&g_agg[(size_t)n_a * 32 + col]) =
                        make_float2(d[0], d[1]);
                if (n_b < n_nodes)
                    *reinterpret_cast<float2*>(&g_agg[(size_t)n_b * 32 + col]) =
                        make_float2(d[2], d[3]);
            }
        }
    }
}

// ---------------------------------------------------------------------------
// K2: edge stage. 8 edges per warp (two quads, gathers issued up-front);
// 8 lanes per edge; each lane covers 4 output columns.
// g_Ph layout: [n][col][basis] -> per lane 2x LDG.128.
// ---------------------------------------------------------------------------
__global__ void __launch_bounds__(256) k_edge(
    const int* __restrict__ esrc, const int* __restrict__ edst,
    const int* __restrict__ etype, const float* __restrict__ w_comp,
    const float* __restrict__ B_w, const float* __restrict__ B_b, int n_edges) {
    __shared__ __align__(16) float4 s_wc[MAX_RELS];
    __shared__ __align__(16) float4 s_t4[MAX_RELS * 8];
    __shared__ __align__(16) float4 s_bw4[8];
    __shared__ float s_bb;

    int tid = threadIdx.x;
    if (tid < MAX_RELS)
        s_wc[tid] = reinterpret_cast<const float4*>(w_comp)[tid];
    if (tid < MAX_RELS * 8)
        s_t4[tid] = reinterpret_cast<const float4*>(g_t)[tid];
    if (tid < 8)
        s_bw4[tid] = reinterpret_cast<const float4*>(B_w)[tid];
    if (tid == 0) s_bb = B_b[0];
    __syncthreads();

    int warp = (blockIdx.x * blockDim.x + tid) >> 5;
    int lane = tid & 31;
    int sub = lane >> 3;
    int g = lane & 7;
    float4 bw = s_bw4[g];

    int src[2], dst[2], ty[2];
    bool ok[2];
#pragma unroll
    for (int q = 0; q < 2; q++) {
        int e = warp * 8 + q * 4 + sub;
        ok[q] = (e < n_edges);
        int ee = ok[q] ? e : 0;
        src[q] = esrc[ee];
        dst[q] = edst[ee];
        ty[q] = etype[ee];
    }
    if (!ok[0]) return;

    // all gathers issued before any consumption (deep MLP)
    uint4 r0[2], r1[2];
    uint2 uu[2], vv[2];
#pragma unroll
    for (int q = 0; q < 2; q++) {
        const uint4* Pp =
            reinterpret_cast<const uint4*>(g_Ph + (size_t)src[q] * 128 + 16 * g);
        r0[q] = Pp[0];
        r1[q] = Pp[1];
        uu[q] = *reinterpret_cast<const uint2*>(g_uh + (size_t)src[q] * 32 + g * 4);
        vv[q] = *reinterpret_cast<const uint2*>(g_vh + (size_t)dst[q] * 32 + g * 4);
    }

#pragma unroll
    for (int q = 0; q < 2; q++) {
        if (!ok[q]) break;
        float4 cc = s_wc[ty[q]];
        float4 t4 = s_t4[ty[q] * 8 + g];

        // cols 4g..4g+3; per col the 4 basis values are contiguous halves
        float2 c0a = __half22float2(*reinterpret_cast<__half2*>(&r0[q].x));
        float2 c0b = __half22float2(*reinterpret_cast<__half2*>(&r0[q].y));
        float2 c1a = __half22float2(*reinterpret_cast<__half2*>(&r0[q].z));
        float2 c1b = __half22float2(*reinterpret_cast<__half2*>(&r0[q].w));
        float2 c2a = __half22float2(*reinterpret_cast<__half2*>(&r1[q].x));
        float2 c2b = __half22float2(*reinterpret_cast<__half2*>(&r1[q].y));
        float2 c3a = __half22float2(*reinterpret_cast<__half2*>(&r1[q].z));
        float2 c3b = __half22float2(*reinterpret_cast<__half2*>(&r1[q].w));

        float4 msg;
        msg.x = c0a.x * cc.x + c0a.y * cc.y + c0b.x * cc.z + c0b.y * cc.w;
        msg.y = c1a.x * cc.x + c1a.y * cc.y + c1b.x * cc.z + c1b.y * cc.w;
        msg.z = c2a.x * cc.x + c2a.y * cc.y + c2b.x * cc.z + c2b.y * cc.w;
        msg.w = c3a.x * cc.x + c3a.y * cc.y + c3b.x * cc.z + c3b.y * cc.w;

        float2 u0 = __half22float2(*reinterpret_cast<__half2*>(&uu[q].x));
        float2 u1 = __half22float2(*reinterpret_cast<__half2*>(&uu[q].y));
        float2 v0 = __half22float2(*reinterpret_cast<__half2*>(&vv[q].x));
        float2 v1 = __half22float2(*reinterpret_cast<__half2*>(&vv[q].y));

        float zx = fmaxf(u0.x + v0.x + t4.x, 0.f);
        float zy = fmaxf(u0.y + v0.y + t4.y, 0.f);
        float zz = fmaxf(u1.x + v1.x + t4.z, 0.f);
        float zw = fmaxf(u1.y + v1.y + t4.w, 0.f);

        float s = zx * bw.x + zy * bw.y + zz * bw.z + zw * bw.w;
        s += __shfl_xor_sync(0xffffffffu, s, 4);
        s += __shfl_xor_sync(0xffffffffu, s, 2);
        s += __shfl_xor_sync(0xffffffffu, s, 1);
        float a = 1.f / (1.f + __expf(-(s + s_bb)));

        float4 r = make_float4(a * msg.x, a * msg.y, a * msg.z, a * msg.w);
        atomicAdd(reinterpret_cast<float4*>(g_agg) + (size_t)dst[q] * 8 + g, r);
    }
}

// ---------------------------------------------------------------------------
// K3: h = relu(agg) -> out[:,1,:]  (float4 vectorized)
// ---------------------------------------------------------------------------
__global__ void k_final(float* __restrict__ out, int n4) {
    int i = blockIdx.x * blockDim.x + threadIdx.x;
    if (i >= n4) return;
    int n = i >> 3;
    int q = i & 7;
    float4 v = reinterpret_cast<const float4*>(g_agg)[i];
    float4 r = make_float4(fmaxf(v.x, 0.f), fmaxf(v.y, 0.f),
                           fmaxf(v.z, 0.f), fmaxf(v.w, 0.f));
    reinterpret_cast<float4*>(out)[(size_t)n * 16 + 8 + q] = r;
}

extern "C" void kernel_launch(void* const* d_in, const int* in_sizes, int n_in,
                              void* d_out, int out_size) {
    const float* feat      = (const float*)d_in[0];
    const float* embed     = (const float*)d_in[1];
    const float* transform = (const float*)d_in[2];
    const float* weight    = (const float*)d_in[3];
    const float* w_comp    = (const float*)d_in[4];
    const float* selfw     = (const float*)d_in[5];
    const float* A_w       = (const float*)d_in[6];
    const float* A_b       = (const float*)d_in[7];
    const float* B_w       = (const float*)d_in[8];
    const float* B_b       = (const float*)d_in[9];
    const float* attn_emb  = (const float*)d_in[10];
    const int*   idx       = (const int*)d_in[11];
    const int*   esrc      = (const int*)d_in[12];
    const int*   edst      = (const int*)d_in[13];
    const int*   ety       = (const int*)d_in[14];
    float* out = (float*)d_out;

    int n_nodes = in_sizes[0] / 32;
    int n_edges = in_sizes[12];

    cudaFuncSetAttribute(k_node, cudaFuncAttributeMaxDynamicSharedMemorySize,
                         SMEM_BYTES);

    int n_tasks = (n_nodes + 15) / 16;          // 3125
    int blocks1 = (n_tasks + 7) / 8;            // 391, one task per warp
    k_node<<<blocks1, 256, SMEM_BYTES>>>(feat, embed, idx, transform, weight,
                                         A_w, selfw, attn_emb, A_b, out,
                                         n_nodes);

    int blocks2 = (n_edges + 63) / 64;          // 8 warps/block, 8 edges/warp
    k_edge<<<blocks2, 256>>>(esrc, edst, ety, w_comp, B_w, B_b, n_edges);

    int n4 = n_nodes * 8;
    int blocks3 = (n4 + 255) / 256;
    k_final<<<blocks3, 256>>>(out, n4);
}